// round 9
// baseline (speedup 1.0000x reference)
#include <cuda_runtime.h>

#define NN 100000
#define EE 1600000
#define DD 64
#define GG 64
#define CAP 96   // ELL row capacity; in-degree is Poisson(16), P(>96) ~ 0

// ---------------- scratch (device-code-only; NEVER passed from host) ---------
__device__ int g_is64;
__device__ int g_degi[NN];
__device__ int g_ell[NN * CAP];
__device__ float g_xs[NN * DD];    // (X @ W) * dinv   (reused both layers)
__device__ float g_h[NN * DD];     // h1 (layer-1 activations)
__device__ float g_pooled[GG * DD];

// ------------------------- index dtype handling ------------------------------
// JAX without x64 downcasts int64 -> int32. If stored int64, every odd 32-bit
// word of edge_index is 0 (node ids < 2^31); if int32 they are random ids.
__device__ __forceinline__ int load_idx(const void* p, int i, int is64) {
    if (is64) return (int)((const long long*)p)[i];
    return ((const int*)p)[i];
}

// ------------- init: dtype detect (block 0) + zero degi/pooled ---------------
__global__ void init_kernel(const int* __restrict__ ei_words) {
    if (blockIdx.x == 0 && threadIdx.x < 32) {
        int w = ei_words[2 * threadIdx.x + 1];
        int any = __any_sync(0xffffffffu, w != 0);
        if (threadIdx.x == 0) g_is64 = any ? 0 : 1;
    }
    int i = blockIdx.x * blockDim.x + threadIdx.x;
    int stride = gridDim.x * blockDim.x;
    for (int j = i; j < NN; j += stride) g_degi[j] = 0;
    for (int j = i; j < GG * DD; j += stride) g_pooled[j] = 0.0f;
}

// ------------------------- ELL adjacency build (dst rows) --------------------
__global__ void fillell_kernel(const void* __restrict__ ei) {
    const int is64 = g_is64;
    int i = blockIdx.x * blockDim.x + threadIdx.x;
    int stride = gridDim.x * blockDim.x;
    for (int e = i; e < EE; e += stride) {
        int s = load_idx(ei, e, is64);
        int d = load_idx(ei, EE + e, is64);
        int slot = atomicAdd(&g_degi[d], 1);
        if (slot < CAP) g_ell[d * CAP + slot] = s;
    }
}

// ------------------------- GEMM: g_xs = (X @ W) * dinv -----------------------
// FIRST: X = harness input x.  else: X = g_h. dinv computed inline from degree.
template <bool FIRST>
__global__ void gemm_kernel(const float* __restrict__ Xext,
                            const float* __restrict__ W) {
    __shared__ float Wsm[DD * DD];
    __shared__ __align__(16) float Xt[DD][36];  // transposed tile, padded
    const int tid = threadIdx.x;                 // 256 threads
    const int row0 = blockIdx.x * 32;

    for (int idx = tid; idx < DD * DD; idx += 256) Wsm[idx] = W[idx];

    for (int idx = tid; idx < 32 * DD; idx += 256) {
        int r = idx >> 6;
        int k = idx & 63;
        int row = row0 + r;
        float v = 0.0f;
        if (row < NN) {
            int g = row * DD + k;
            v = FIRST ? Xext[g] : g_h[g];
        }
        Xt[k][r] = v;
    }
    __syncthreads();

    const int col = tid & 63;
    const int rg = tid >> 6;  // 0..3, each owns 8 rows
    float acc[8];
#pragma unroll
    for (int r = 0; r < 8; r++) acc[r] = 0.f;
#pragma unroll
    for (int k = 0; k < DD; k++) {
        float wv = Wsm[k * DD + col];
        const float4 a = *(const float4*)&Xt[k][rg * 8];
        const float4 b = *(const float4*)&Xt[k][rg * 8 + 4];
        acc[0] += a.x * wv; acc[1] += a.y * wv;
        acc[2] += a.z * wv; acc[3] += a.w * wv;
        acc[4] += b.x * wv; acc[5] += b.y * wv;
        acc[6] += b.z * wv; acc[7] += b.w * wv;
    }

#pragma unroll
    for (int r = 0; r < 8; r++) {
        int row = row0 + rg * 8 + r;
        if (row < NN) {
            float dv = rsqrtf((float)(g_degi[row] + 1));
            g_xs[row * DD + col] = acc[r] * dv;
        }
    }
}

// ------- gather: h[d] = relu(dinv[d]*(sum_{src->d} xs[src] + xs[d]) + b) -----
// Half-warp per dst node; lane owns a float4 column slice.
// POOL: instead of writing h2, red.add the row into g_pooled[batch[d]].
template <bool POOL>
__global__ void gather_kernel(const float* __restrict__ bias,
                              const void* __restrict__ batch) {
    int t = blockIdx.x * blockDim.x + threadIdx.x;
    int node = t >> 4;
    int lane = threadIdx.x & 15;
    if (node >= NN) return;
    const int deg = g_degi[node];
    const int degc = min(deg, CAP);
    const int* row = g_ell + node * CAP;

    float4 a0 = *(const float4*)(g_xs + node * DD + lane * 4);  // self loop
    float4 a1 = make_float4(0.0f, 0.0f, 0.0f, 0.0f);
    int j = 0;
    for (; j + 2 <= degc; j += 2) {
        int s0 = __ldg(&row[j]);
        int s1 = __ldg(&row[j + 1]);
        float4 v0 = *(const float4*)(g_xs + s0 * DD + lane * 4);
        float4 v1 = *(const float4*)(g_xs + s1 * DD + lane * 4);
        a0.x += v0.x; a0.y += v0.y; a0.z += v0.z; a0.w += v0.w;
        a1.x += v1.x; a1.y += v1.y; a1.z += v1.z; a1.w += v1.w;
    }
    if (j < degc) {
        int s = __ldg(&row[j]);
        float4 v = *(const float4*)(g_xs + s * DD + lane * 4);
        a0.x += v.x; a0.y += v.y; a0.z += v.z; a0.w += v.w;
    }

    const float dv = rsqrtf((float)(deg + 1));
    const float4 b = *(const float4*)(bias + lane * 4);
    float4 h;
    h.x = fmaxf(dv * (a0.x + a1.x) + b.x, 0.0f);
    h.y = fmaxf(dv * (a0.y + a1.y) + b.y, 0.0f);
    h.z = fmaxf(dv * (a0.z + a1.z) + b.z, 0.0f);
    h.w = fmaxf(dv * (a0.w + a1.w) + b.w, 0.0f);

    if (POOL) {
        int bg = load_idx(batch, node, g_is64);
        float* addr = g_pooled + bg * DD + lane * 4;
        asm volatile("red.global.add.v2.f32 [%0], {%1, %2};"
                     :: "l"(addr), "f"(h.x), "f"(h.y) : "memory");
        asm volatile("red.global.add.v2.f32 [%0], {%1, %2};"
                     :: "l"(addr + 2), "f"(h.z), "f"(h.w) : "memory");
    } else {
        *(float4*)(g_h + node * DD + lane * 4) = h;
    }
}

// -------- head: counts via binary search (batch sorted) + FC + log_softmax ---
__device__ __forceinline__ int lower_bound_batch(const void* batch, int key, int is64) {
    int lo = 0, hi = NN;
    while (lo < hi) {
        int mid = (lo + hi) >> 1;
        if (load_idx(batch, mid, is64) < key) lo = mid + 1;
        else hi = mid;
    }
    return lo;
}

__global__ void head_kernel(const void* __restrict__ batch,
                            const float* __restrict__ Wfc,
                            const float* __restrict__ bfc,
                            float* __restrict__ out) {
    int g = threadIdx.x;
    if (g >= GG) return;
    const int is64 = g_is64;
    int c0 = lower_bound_batch(batch, g, is64);
    int c1 = lower_bound_batch(batch, g + 1, is64);
    float inv = 1.0f / fmaxf((float)(c1 - c0), 1.0f);

    float l0 = __ldg(&bfc[0]), l1 = __ldg(&bfc[1]);
#pragma unroll
    for (int k = 0; k < DD; k++) {
        float p = g_pooled[g * DD + k] * inv;
        l0 += p * __ldg(&Wfc[k * 2]);
        l1 += p * __ldg(&Wfc[k * 2 + 1]);
    }
    float m = fmaxf(l0, l1);
    float lse = m + logf(expf(l0 - m) + expf(l1 - m));
    out[g * 2 + 0] = l0 - lse;
    out[g * 2 + 1] = l1 - lse;
}

// ------------------------- launch --------------------------------------------
extern "C" void kernel_launch(void* const* d_in, const int* in_sizes, int n_in,
                              void* d_out, int out_size) {
    // Resolve inputs by element count (robust to metadata ordering).
    const float *x = 0, *W1 = 0, *b1 = 0, *W2 = 0, *b2 = 0, *Wfc = 0, *bfc = 0;
    const void *ei = 0, *batch = 0;
    for (int i = 0; i < n_in; i++) {
        int s = in_sizes[i];
        if (s == NN * DD)      x = (const float*)d_in[i];
        else if (s == 2 * EE)  ei = d_in[i];
        else if (s == NN)      batch = d_in[i];
        else if (s == DD * DD) { if (!W1) W1 = (const float*)d_in[i]; else W2 = (const float*)d_in[i]; }
        else if (s == DD)      { if (!b1) b1 = (const float*)d_in[i]; else b2 = (const float*)d_in[i]; }
        else if (s == DD * 2)  Wfc = (const float*)d_in[i];
        else if (s == 2)       bfc = (const float*)d_in[i];
    }
    float* out = (float*)d_out;

    init_kernel<<<512, 256>>>((const int*)ei);
    fillell_kernel<<<2048, 256>>>(ei);

    gemm_kernel<true><<<(NN + 31) / 32, 256>>>(x, W1);
    gather_kernel<false><<<(NN * 16 + 255) / 256, 256>>>(b1, batch);

    gemm_kernel<false><<<(NN + 31) / 32, 256>>>(nullptr, W2);
    gather_kernel<true><<<(NN * 16 + 255) / 256, 256>>>(b2, batch);

    head_kernel<<<1, 64>>>(batch, Wfc, bfc, out);
}

// round 10
// speedup vs baseline: 1.1930x; 1.1930x over previous
#include <cuda_runtime.h>

#define NN 100000
#define EE 1600000
#define DD 64
#define GG 64
#define CAP 96   // ELL row capacity; in-degree is Poisson(16), P(>96) ~ 0

// ---------------- scratch (device-code-only; NEVER passed from host) ---------
__device__ int g_is64;
__device__ int g_degi[NN];
__device__ int g_ell[NN * CAP];
__device__ float g_xs[NN * DD];    // (X @ W) * dinv   (reused both layers)
__device__ float g_h[NN * DD];     // h1, then h2
__device__ float g_pooled[GG * DD];

// ------------------------- index dtype handling ------------------------------
__device__ __forceinline__ int load_idx(const void* p, int i, int is64) {
    if (is64) return (int)((const long long*)p)[i];
    return ((const int*)p)[i];
}

// ------------- init: dtype detect (block 0) + zero degi/pooled ---------------
__global__ void init_kernel(const int* __restrict__ ei_words) {
    if (blockIdx.x == 0 && threadIdx.x < 32) {
        int w = ei_words[2 * threadIdx.x + 1];
        int any = __any_sync(0xffffffffu, w != 0);
        if (threadIdx.x == 0) g_is64 = any ? 0 : 1;
    }
    int i = blockIdx.x * blockDim.x + threadIdx.x;
    int stride = gridDim.x * blockDim.x;
    for (int j = i; j < NN; j += stride) g_degi[j] = 0;
    for (int j = i; j < GG * DD; j += stride) g_pooled[j] = 0.0f;
}

// ------------------------- ELL adjacency build (dst rows) --------------------
__global__ void fillell_kernel(const void* __restrict__ ei) {
    const int is64 = g_is64;
    int i = blockIdx.x * blockDim.x + threadIdx.x;
    int stride = gridDim.x * blockDim.x;
    for (int e = i; e < EE; e += stride) {
        int s = load_idx(ei, e, is64);
        int d = load_idx(ei, EE + e, is64);
        int slot = atomicAdd(&g_degi[d], 1);
        if (slot < CAP) g_ell[d * CAP + slot] = s;
    }
}

// ------------------------- GEMM: g_xs = (X @ W) * dinv -----------------------
template <bool FIRST>
__global__ void gemm_kernel(const float* __restrict__ Xext,
                            const float* __restrict__ W) {
    __shared__ float Wsm[DD * DD];
    __shared__ __align__(16) float Xt[DD][36];  // transposed tile, padded
    const int tid = threadIdx.x;                 // 256 threads
    const int row0 = blockIdx.x * 32;

    for (int idx = tid; idx < DD * DD; idx += 256) Wsm[idx] = W[idx];

    for (int idx = tid; idx < 32 * DD; idx += 256) {
        int r = idx >> 6;
        int k = idx & 63;
        int row = row0 + r;
        float v = 0.0f;
        if (row < NN) {
            int g = row * DD + k;
            v = FIRST ? Xext[g] : g_h[g];
        }
        Xt[k][r] = v;
    }
    __syncthreads();

    const int col = tid & 63;
    const int rg = tid >> 6;  // 0..3, each owns 8 rows
    float acc[8];
#pragma unroll
    for (int r = 0; r < 8; r++) acc[r] = 0.f;
#pragma unroll
    for (int k = 0; k < DD; k++) {
        float wv = Wsm[k * DD + col];
        const float4 a = *(const float4*)&Xt[k][rg * 8];
        const float4 b = *(const float4*)&Xt[k][rg * 8 + 4];
        acc[0] += a.x * wv; acc[1] += a.y * wv;
        acc[2] += a.z * wv; acc[3] += a.w * wv;
        acc[4] += b.x * wv; acc[5] += b.y * wv;
        acc[6] += b.z * wv; acc[7] += b.w * wv;
    }

#pragma unroll
    for (int r = 0; r < 8; r++) {
        int row = row0 + rg * 8 + r;
        if (row < NN) {
            float dv = rsqrtf((float)(g_degi[row] + 1));
            g_xs[row * DD + col] = acc[r] * dv;
        }
    }
}

// ------- gather: h[d] = relu(dinv[d]*(sum_{src->d} xs[src] + xs[d]) + b) -----
// Half-warp per dst node; lane owns a float4 column slice; 4-way edge ILP.
__global__ void gather_kernel(const float* __restrict__ bias) {
    int t = blockIdx.x * blockDim.x + threadIdx.x;
    int node = t >> 4;
    int lane = threadIdx.x & 15;
    if (node >= NN) return;
    const int deg = g_degi[node];
    const int degc = min(deg, CAP);
    const int* row = g_ell + node * CAP;

    float4 a0 = *(const float4*)(g_xs + node * DD + lane * 4);  // self loop
    float4 a1 = make_float4(0.f, 0.f, 0.f, 0.f);
    float4 a2 = make_float4(0.f, 0.f, 0.f, 0.f);
    float4 a3 = make_float4(0.f, 0.f, 0.f, 0.f);
    int j = 0;
    for (; j + 4 <= degc; j += 4) {
        int s0 = __ldg(&row[j + 0]);
        int s1 = __ldg(&row[j + 1]);
        int s2 = __ldg(&row[j + 2]);
        int s3 = __ldg(&row[j + 3]);
        float4 v0 = *(const float4*)(g_xs + s0 * DD + lane * 4);
        float4 v1 = *(const float4*)(g_xs + s1 * DD + lane * 4);
        float4 v2 = *(const float4*)(g_xs + s2 * DD + lane * 4);
        float4 v3 = *(const float4*)(g_xs + s3 * DD + lane * 4);
        a0.x += v0.x; a0.y += v0.y; a0.z += v0.z; a0.w += v0.w;
        a1.x += v1.x; a1.y += v1.y; a1.z += v1.z; a1.w += v1.w;
        a2.x += v2.x; a2.y += v2.y; a2.z += v2.z; a2.w += v2.w;
        a3.x += v3.x; a3.y += v3.y; a3.z += v3.z; a3.w += v3.w;
    }
    for (; j < degc; j++) {
        int s = __ldg(&row[j]);
        float4 v = *(const float4*)(g_xs + s * DD + lane * 4);
        a0.x += v.x; a0.y += v.y; a0.z += v.z; a0.w += v.w;
    }

    const float dv = rsqrtf((float)(deg + 1));
    const float4 b = *(const float4*)(bias + lane * 4);
    float4 h;
    h.x = fmaxf(dv * ((a0.x + a1.x) + (a2.x + a3.x)) + b.x, 0.0f);
    h.y = fmaxf(dv * ((a0.y + a1.y) + (a2.y + a3.y)) + b.y, 0.0f);
    h.z = fmaxf(dv * ((a0.z + a1.z) + (a2.z + a3.z)) + b.z, 0.0f);
    h.w = fmaxf(dv * ((a0.w + a1.w) + (a2.w + a3.w)) + b.w, 0.0f);
    *(float4*)(g_h + node * DD + lane * 4) = h;
}

// --------------- mean-pool numerator over sorted batch ids (reads g_h) -------
__global__ void pool_kernel(const void* __restrict__ batch) {
    const int is64 = g_is64;
    const int c = threadIdx.x;  // 64 threads, one per feature
    const int start = blockIdx.x * 128;
    if (start >= NN) return;
    const int end = min(start + 128, NN);
    float acc = 0.f;
    int curg = load_idx(batch, start, is64);
    for (int i = start; i < end; i++) {
        int g = load_idx(batch, i, is64);
        if (g != curg) {
            atomicAdd(&g_pooled[curg * DD + c], acc);
            acc = 0.f; curg = g;
        }
        acc += g_h[i * DD + c];
    }
    atomicAdd(&g_pooled[curg * DD + c], acc);
}

// -------- head: counts via binary search (batch sorted) + FC + log_softmax ---
__device__ __forceinline__ int lower_bound_batch(const void* batch, int key, int is64) {
    int lo = 0, hi = NN;
    while (lo < hi) {
        int mid = (lo + hi) >> 1;
        if (load_idx(batch, mid, is64) < key) lo = mid + 1;
        else hi = mid;
    }
    return lo;
}

__global__ void head_kernel(const void* __restrict__ batch,
                            const float* __restrict__ Wfc,
                            const float* __restrict__ bfc,
                            float* __restrict__ out) {
    int g = threadIdx.x;
    if (g >= GG) return;
    const int is64 = g_is64;
    int c0 = lower_bound_batch(batch, g, is64);
    int c1 = lower_bound_batch(batch, g + 1, is64);
    float inv = 1.0f / fmaxf((float)(c1 - c0), 1.0f);

    float l0 = __ldg(&bfc[0]), l1 = __ldg(&bfc[1]);
#pragma unroll
    for (int k = 0; k < DD; k++) {
        float p = g_pooled[g * DD + k] * inv;
        l0 += p * __ldg(&Wfc[k * 2]);
        l1 += p * __ldg(&Wfc[k * 2 + 1]);
    }
    float m = fmaxf(l0, l1);
    float lse = m + logf(expf(l0 - m) + expf(l1 - m));
    out[g * 2 + 0] = l0 - lse;
    out[g * 2 + 1] = l1 - lse;
}

// ------------------------- launch --------------------------------------------
extern "C" void kernel_launch(void* const* d_in, const int* in_sizes, int n_in,
                              void* d_out, int out_size) {
    // Resolve inputs by element count (robust to metadata ordering).
    const float *x = 0, *W1 = 0, *b1 = 0, *W2 = 0, *b2 = 0, *Wfc = 0, *bfc = 0;
    const void *ei = 0, *batch = 0;
    for (int i = 0; i < n_in; i++) {
        int s = in_sizes[i];
        if (s == NN * DD)      x = (const float*)d_in[i];
        else if (s == 2 * EE)  ei = d_in[i];
        else if (s == NN)      batch = d_in[i];
        else if (s == DD * DD) { if (!W1) W1 = (const float*)d_in[i]; else W2 = (const float*)d_in[i]; }
        else if (s == DD)      { if (!b1) b1 = (const float*)d_in[i]; else b2 = (const float*)d_in[i]; }
        else if (s == DD * 2)  Wfc = (const float*)d_in[i];
        else if (s == 2)       bfc = (const float*)d_in[i];
    }
    float* out = (float*)d_out;

    init_kernel<<<512, 256>>>((const int*)ei);
    fillell_kernel<<<2048, 256>>>(ei);

    gemm_kernel<true><<<(NN + 31) / 32, 256>>>(x, W1);
    gather_kernel<<<(NN * 16 + 255) / 256, 256>>>(b1);

    gemm_kernel<false><<<(NN + 31) / 32, 256>>>(nullptr, W2);
    gather_kernel<<<(NN * 16 + 255) / 256, 256>>>(b2);

    pool_kernel<<<(NN + 127) / 128, 64>>>(batch);
    head_kernel<<<1, 64>>>(batch, Wfc, bfc, out);
}

// round 11
// speedup vs baseline: 1.2407x; 1.0400x over previous
#include <cuda_runtime.h>

#define NN 100000
#define EE 1600000
#define DD 64
#define GG 64
#define CAP 96   // ELL row capacity; in-degree is Poisson(16), P(>96) ~ 0

// ---------------- scratch (device-code-only; NEVER passed from host) ---------
__device__ int g_is64;
__device__ int g_degi[NN];
__device__ int g_ell[NN * CAP];
__device__ float g_xs[NN * DD];    // (X @ W) * dinv   (reused both layers)
__device__ float g_h[NN * DD];     // h1, then h2
__device__ float g_pooled[GG * DD];

// ------------------------- index dtype handling ------------------------------
__device__ __forceinline__ int load_idx(const void* p, int i, int is64) {
    if (is64) return (int)((const long long*)p)[i];
    return ((const int*)p)[i];
}

// ------------- init: dtype detect (block 0) + zero degi/pooled ---------------
__global__ void init_kernel(const int* __restrict__ ei_words) {
    if (blockIdx.x == 0 && threadIdx.x < 32) {
        int w = ei_words[2 * threadIdx.x + 1];
        int any = __any_sync(0xffffffffu, w != 0);
        if (threadIdx.x == 0) g_is64 = any ? 0 : 1;
    }
    int i = blockIdx.x * blockDim.x + threadIdx.x;
    int stride = gridDim.x * blockDim.x;
    for (int j = i; j < NN; j += stride) g_degi[j] = 0;
    for (int j = i; j < GG * DD; j += stride) g_pooled[j] = 0.0f;
}

// ------------------------- ELL adjacency build (dst rows) --------------------
__global__ void fillell_kernel(const void* __restrict__ ei) {
    const int is64 = g_is64;
    int i = blockIdx.x * blockDim.x + threadIdx.x;
    int stride = gridDim.x * blockDim.x;
    for (int e = i; e < EE; e += stride) {
        int s = load_idx(ei, e, is64);
        int d = load_idx(ei, EE + e, is64);
        int slot = atomicAdd(&g_degi[d], 1);
        if (slot < CAP) g_ell[d * CAP + slot] = s;
    }
}

// ------------------------- GEMM: g_xs = (X @ W) * dinv -----------------------
template <bool FIRST>
__global__ void gemm_kernel(const float* __restrict__ Xext,
                            const float* __restrict__ W) {
    __shared__ float Wsm[DD * DD];
    __shared__ __align__(16) float Xt[DD][36];  // transposed tile, padded
    const int tid = threadIdx.x;                 // 256 threads
    const int row0 = blockIdx.x * 32;

    for (int idx = tid; idx < DD * DD; idx += 256) Wsm[idx] = W[idx];

    for (int idx = tid; idx < 32 * DD; idx += 256) {
        int r = idx >> 6;
        int k = idx & 63;
        int row = row0 + r;
        float v = 0.0f;
        if (row < NN) {
            int g = row * DD + k;
            v = FIRST ? Xext[g] : g_h[g];
        }
        Xt[k][r] = v;
    }
    __syncthreads();

    const int col = tid & 63;
    const int rg = tid >> 6;  // 0..3, each owns 8 rows
    float acc[8];
#pragma unroll
    for (int r = 0; r < 8; r++) acc[r] = 0.f;
#pragma unroll
    for (int k = 0; k < DD; k++) {
        float wv = Wsm[k * DD + col];
        const float4 a = *(const float4*)&Xt[k][rg * 8];
        const float4 b = *(const float4*)&Xt[k][rg * 8 + 4];
        acc[0] += a.x * wv; acc[1] += a.y * wv;
        acc[2] += a.z * wv; acc[3] += a.w * wv;
        acc[4] += b.x * wv; acc[5] += b.y * wv;
        acc[6] += b.z * wv; acc[7] += b.w * wv;
    }

#pragma unroll
    for (int r = 0; r < 8; r++) {
        int row = row0 + rg * 8 + r;
        if (row < NN) {
            float dv = rsqrtf((float)(g_degi[row] + 1));
            g_xs[row * DD + col] = acc[r] * dv;
        }
    }
}

// ------- gather: h[d] = relu(dinv[d]*(sum_{src->d} xs[src] + xs[d]) + b) -----
// Half-warp per dst node; lane owns a float4 column slice; 2-way edge ILP.
// (Measured best shape: 32 regs, occ 81%, 38.7us. 4-way ILP regressed via
//  register pressure -> occupancy loss; do not re-widen.)
__global__ void __launch_bounds__(256, 8) gather_kernel(const float* __restrict__ bias) {
    int t = blockIdx.x * blockDim.x + threadIdx.x;
    int node = t >> 4;
    int lane = threadIdx.x & 15;
    if (node >= NN) return;
    const int deg = g_degi[node];
    const int degc = min(deg, CAP);
    const int* row = g_ell + node * CAP;

    float4 a0 = *(const float4*)(g_xs + node * DD + lane * 4);  // self loop
    float4 a1 = make_float4(0.0f, 0.0f, 0.0f, 0.0f);
    int j = 0;
    for (; j + 2 <= degc; j += 2) {
        int s0 = __ldg(&row[j]);
        int s1 = __ldg(&row[j + 1]);
        float4 v0 = *(const float4*)(g_xs + s0 * DD + lane * 4);
        float4 v1 = *(const float4*)(g_xs + s1 * DD + lane * 4);
        a0.x += v0.x; a0.y += v0.y; a0.z += v0.z; a0.w += v0.w;
        a1.x += v1.x; a1.y += v1.y; a1.z += v1.z; a1.w += v1.w;
    }
    if (j < degc) {
        int s = __ldg(&row[j]);
        float4 v = *(const float4*)(g_xs + s * DD + lane * 4);
        a0.x += v.x; a0.y += v.y; a0.z += v.z; a0.w += v.w;
    }

    const float dv = rsqrtf((float)(deg + 1));
    const float4 b = *(const float4*)(bias + lane * 4);
    float4 h;
    h.x = fmaxf(dv * (a0.x + a1.x) + b.x, 0.0f);
    h.y = fmaxf(dv * (a0.y + a1.y) + b.y, 0.0f);
    h.z = fmaxf(dv * (a0.z + a1.z) + b.z, 0.0f);
    h.w = fmaxf(dv * (a0.w + a1.w) + b.w, 0.0f);
    *(float4*)(g_h + node * DD + lane * 4) = h;
}

// --------------- mean-pool numerator over sorted batch ids (reads g_h) -------
__global__ void pool_kernel(const void* __restrict__ batch) {
    const int is64 = g_is64;
    const int c = threadIdx.x;  // 64 threads, one per feature
    const int start = blockIdx.x * 128;
    if (start >= NN) return;
    const int end = min(start + 128, NN);
    float acc = 0.f;
    int curg = load_idx(batch, start, is64);
    for (int i = start; i < end; i++) {
        int g = load_idx(batch, i, is64);
        if (g != curg) {
            atomicAdd(&g_pooled[curg * DD + c], acc);
            acc = 0.f; curg = g;
        }
        acc += g_h[i * DD + c];
    }
    atomicAdd(&g_pooled[curg * DD + c], acc);
}

// -------- head: counts via binary search (batch sorted) + FC + log_softmax ---
__device__ __forceinline__ int lower_bound_batch(const void* batch, int key, int is64) {
    int lo = 0, hi = NN;
    while (lo < hi) {
        int mid = (lo + hi) >> 1;
        if (load_idx(batch, mid, is64) < key) lo = mid + 1;
        else hi = mid;
    }
    return lo;
}

__global__ void head_kernel(const void* __restrict__ batch,
                            const float* __restrict__ Wfc,
                            const float* __restrict__ bfc,
                            float* __restrict__ out) {
    int g = threadIdx.x;
    if (g >= GG) return;
    const int is64 = g_is64;
    int c0 = lower_bound_batch(batch, g, is64);
    int c1 = lower_bound_batch(batch, g + 1, is64);
    float inv = 1.0f / fmaxf((float)(c1 - c0), 1.0f);

    float l0 = __ldg(&bfc[0]), l1 = __ldg(&bfc[1]);
#pragma unroll
    for (int k = 0; k < DD; k++) {
        float p = g_pooled[g * DD + k] * inv;
        l0 += p * __ldg(&Wfc[k * 2]);
        l1 += p * __ldg(&Wfc[k * 2 + 1]);
    }
    float m = fmaxf(l0, l1);
    float lse = m + logf(expf(l0 - m) + expf(l1 - m));
    out[g * 2 + 0] = l0 - lse;
    out[g * 2 + 1] = l1 - lse;
}

// ------------------------- launch --------------------------------------------
extern "C" void kernel_launch(void* const* d_in, const int* in_sizes, int n_in,
                              void* d_out, int out_size) {
    // Resolve inputs by element count (robust to metadata ordering).
    const float *x = 0, *W1 = 0, *b1 = 0, *W2 = 0, *b2 = 0, *Wfc = 0, *bfc = 0;
    const void *ei = 0, *batch = 0;
    for (int i = 0; i < n_in; i++) {
        int s = in_sizes[i];
        if (s == NN * DD)      x = (const float*)d_in[i];
        else if (s == 2 * EE)  ei = d_in[i];
        else if (s == NN)      batch = d_in[i];
        else if (s == DD * DD) { if (!W1) W1 = (const float*)d_in[i]; else W2 = (const float*)d_in[i]; }
        else if (s == DD)      { if (!b1) b1 = (const float*)d_in[i]; else b2 = (const float*)d_in[i]; }
        else if (s == DD * 2)  Wfc = (const float*)d_in[i];
        else if (s == 2)       bfc = (const float*)d_in[i];
    }
    float* out = (float*)d_out;

    init_kernel<<<512, 256>>>((const int*)ei);
    fillell_kernel<<<2048, 256>>>(ei);

    gemm_kernel<true><<<(NN + 31) / 32, 256>>>(x, W1);
    gather_kernel<<<(NN * 16 + 255) / 256, 256>>>(b1);

    gemm_kernel<false><<<(NN + 31) / 32, 256>>>(nullptr, W2);
    gather_kernel<<<(NN * 16 + 255) / 256, 256>>>(b2);

    pool_kernel<<<(NN + 127) / 128, 64>>>(batch);
    head_kernel<<<1, 64>>>(batch, Wfc, bfc, out);
}